// round 4
// baseline (speedup 1.0000x reference)
#include <cuda_runtime.h>
#include <cstdint>

#define NN 512
#define GRID 148
#define TPB 128
#define TILES 8192

// ---- SMEM float offsets ----
#define OFF_W1T 0       // W1^T [n=128][k=64]  stride 68  -> 8704
#define OFF_W2T 8704    // W2^T [n=128][h=128] stride 132 -> 16896
#define OFF_YS  25600   // y tile [128][64]    stride 68  -> 8704
#define OFF_DH  34304   // D/H union [128][132]           -> 16896
#define OFF_TV  51200   // tv[4][128]
#define OFF_B2S 51712
#define OFF_W3S 51840
#define SMEM_FLOATS 51968   // 207872 bytes

__device__ __forceinline__ uint32_t cvt_tf32(float f) {
    uint32_t u; asm("cvt.rna.tf32.f32 %0, %1;" : "=r"(u) : "f"(f)); return u;
}
__device__ __forceinline__ uint32_t smem_u32(const void* p) {
    uint32_t a;
    asm("{ .reg .u64 t; cvta.to.shared.u64 t, %1; cvt.u32.u64 %0, t; }" : "=r"(a) : "l"(p));
    return a;
}
__device__ __forceinline__ void ldsm_x4(uint32_t& r0, uint32_t& r1, uint32_t& r2, uint32_t& r3,
                                        uint32_t addr) {
    asm volatile("ldmatrix.sync.aligned.m8n8.x4.shared.b16 {%0,%1,%2,%3}, [%4];"
                 : "=r"(r0), "=r"(r1), "=r"(r2), "=r"(r3) : "r"(addr));
}
__device__ __forceinline__ void mma_tf32(float* c,
                                         uint32_t a0, uint32_t a1, uint32_t a2, uint32_t a3,
                                         uint32_t b0, uint32_t b1) {
    asm volatile("mma.sync.aligned.m16n8k8.row.col.f32.tf32.tf32.f32 "
                 "{%0,%1,%2,%3},{%4,%5,%6,%7},{%8,%9},{%0,%1,%2,%3};"
                 : "+f"(c[0]), "+f"(c[1]), "+f"(c[2]), "+f"(c[3])
                 : "r"(a0), "r"(a1), "r"(a2), "r"(a3), "r"(b0), "r"(b1));
}

__global__ void __launch_bounds__(TPB, 1)
pairmlp_mma(const float* __restrict__ x, const float* __restrict__ y,
            const float* __restrict__ t, const float* __restrict__ W1,
            const float* __restrict__ b1, const float* __restrict__ W2,
            const float* __restrict__ b2, const float* __restrict__ W3,
            const float* __restrict__ b3, float* __restrict__ out)
{
    extern __shared__ float s[];
    const int tid = threadIdx.x;
    const int wid = tid >> 5;
    const int l   = tid & 31;
    const int m32 = wid * 32;          // warp owns 32 j-rows
    const uint32_t sb = smem_u32(s);

    // ---- one-time staging ----
    for (int idx = tid; idx < 64 * 128; idx += TPB) {
        int k = idx >> 7, n = idx & 127;
        ((uint32_t*)s)[OFF_W1T + n * 68 + k] = cvt_tf32(W1[k * 128 + n]);
    }
    for (int idx = tid; idx < 128 * 128; idx += TPB) {
        int h = idx >> 7, n = idx & 127;
        ((uint32_t*)s)[OFF_W2T + n * 132 + h] = cvt_tf32(W2[h * 128 + n]);
    }
    for (int idx = tid; idx < 4 * 128; idx += TPB) {
        int bb = idx >> 7, h = idx & 127;
        float sum = b1[h];
        #pragma unroll
        for (int d = 0; d < 32; d++) sum += t[bb * 32 + d] * W1[(64 + d) * 128 + h];
        s[OFF_TV + idx] = sum;
    }
    if (tid < 128) { s[OFF_B2S + tid] = b2[tid]; s[OFF_W3S + tid] = W3[tid]; }
    const float b3v = b3[0];
    __syncthreads();

    // ---- per-lane ldmatrix base addresses (bytes) ----
    const int g = l >> 3, r = l & 7;
    // A fragment (16x8): m0 rows0-7/k0-3, m1 rows8-15/k0-3, m2 rows0-7/k4-7, m3 rows8-15/k4-7
    const uint32_t aRow0 = (uint32_t)(m32 + (g & 1) * 8 + r);
    const uint32_t aA0 = sb + (OFF_DH + aRow0 * 132) * 4 + (uint32_t)(g >> 1) * 16;
    const uint32_t aA1 = aA0 + 16 * 132 * 4;   // second 16-row block
    // B fragment pair: m0 (n0..7,k0), m1 (n0..7,k0+4), m2 (n0+8..15,k0), m3 (n0+8..15,k0+4)
    const uint32_t bn  = (uint32_t)((g >> 1) * 8 + r);
    const uint32_t bCb = (uint32_t)(g & 1) * 16;
    const uint32_t bB1 = sb + (OFF_W1T + bn * 68) * 4 + bCb;
    const uint32_t bB2 = sb + (OFF_W2T + bn * 132) * 4 + bCb;

    const int start = (TILES * blockIdx.x) / GRID;
    const int end   = (TILES * (blockIdx.x + 1)) / GRID;
    int cur_bjt = -1;

    const int qr = l >> 2;        // quad row 0..7
    const int qc = l & 3;         // quad col 0..3

    for (int tau = start; tau < end; ++tau) {
        const int b  = tau >> 11;
        const int jt = (tau >> 9) & 3;
        const int i  = tau & 511;
        const int bjt = tau >> 9;

        if (bjt != cur_bjt) {
            __syncthreads();     // drain readers of old ys
            const float4* yg = (const float4*)(y + ((size_t)(b * NN + jt * 128)) * 64);
            for (int idx = tid; idx < 128 * 16; idx += TPB) {
                int rr = idx >> 4, gg = idx & 15;
                float4 v = yg[rr * 16 + gg];
                float* dst = s + OFF_YS + rr * 68 + gg * 4;
                dst[0] = v.x; dst[1] = v.y; dst[2] = v.z; dst[3] = v.w;
            }
            cur_bjt = bjt;
            __syncthreads();
        }

        // ---- diff^2 -> DH strip (warp-private rows m32..m32+31) ----
        {
            const float4* xg = (const float4*)(x + ((size_t)(b * NN + i)) * 64 + qc * 16);
            float4 xv[4];
            #pragma unroll
            for (int q = 0; q < 4; q++) xv[q] = xg[q];
            #pragma unroll
            for (int rr = 0; rr < 4; rr++) {
                int row = m32 + qr + rr * 8;
                const float4* yrow = (const float4*)(s + OFF_YS + row * 68 + qc * 16);
                uint32_t* drow = (uint32_t*)s + OFF_DH + row * 132 + qc * 16;
                #pragma unroll
                for (int q = 0; q < 4; q++) {
                    float4 yv = yrow[q];
                    float d0 = xv[q].x - yv.x, d1 = xv[q].y - yv.y;
                    float d2 = xv[q].z - yv.z, d3 = xv[q].w - yv.w;
                    uint4 w;
                    w.x = cvt_tf32(d0 * d0); w.y = cvt_tf32(d1 * d1);
                    w.z = cvt_tf32(d2 * d2); w.w = cvt_tf32(d3 * d3);
                    *(uint4*)(drow + q * 4) = w;
                }
            }
        }
        __syncwarp();

        float acc[2][16][4];
        #pragma unroll
        for (int hb = 0; hb < 2; hb++)
            #pragma unroll
            for (int nt = 0; nt < 16; nt++)
                #pragma unroll
                for (int c = 0; c < 4; c++) acc[hb][nt][c] = 0.f;

        // ---- GEMM1: K=64 (8 k-steps), N=128, M=32 ----
        #pragma unroll
        for (int k = 0; k < 8; k++) {
            uint32_t a0, a1, a2, a3, e0, e1, e2, e3;
            ldsm_x4(a0, a1, a2, a3, aA0 + k * 32);
            ldsm_x4(e0, e1, e2, e3, aA1 + k * 32);
            #pragma unroll
            for (int p = 0; p < 8; p++) {
                uint32_t b0, b1v, b2v, b3r;
                ldsm_x4(b0, b1v, b2v, b3r, bB1 + p * 4352 + k * 32);
                mma_tf32(acc[0][2 * p],     a0, a1, a2, a3, b0, b1v);
                mma_tf32(acc[0][2 * p + 1], a0, a1, a2, a3, b2v, b3r);
                mma_tf32(acc[1][2 * p],     e0, e1, e2, e3, b0, b1v);
                mma_tf32(acc[1][2 * p + 1], e0, e1, e2, e3, b2v, b3r);
            }
        }
        __syncwarp();

        // ---- epilogue1: H = tf32(relu(C1 + tv)), overwrite DH strip ----
        {
            const float* tvb = s + OFF_TV + b * 128;
            #pragma unroll
            for (int nt = 0; nt < 16; nt++) {
                int h0 = nt * 8 + 2 * qc;
                float2 tvv = *(const float2*)(tvb + h0);
                #pragma unroll
                for (int hb = 0; hb < 2; hb++) {
                    float v0 = fmaxf(acc[hb][nt][0] + tvv.x, 0.f);
                    float v1 = fmaxf(acc[hb][nt][1] + tvv.y, 0.f);
                    float v2 = fmaxf(acc[hb][nt][2] + tvv.x, 0.f);
                    float v3 = fmaxf(acc[hb][nt][3] + tvv.y, 0.f);
                    uint2 w01; w01.x = cvt_tf32(v0); w01.y = cvt_tf32(v1);
                    uint2 w23; w23.x = cvt_tf32(v2); w23.y = cvt_tf32(v3);
                    int rbase = m32 + hb * 16 + qr;
                    *(uint2*)((uint32_t*)s + OFF_DH + rbase * 132 + h0)       = w01;
                    *(uint2*)((uint32_t*)s + OFF_DH + (rbase + 8) * 132 + h0) = w23;
                    acc[hb][nt][0] = 0.f; acc[hb][nt][1] = 0.f;
                    acc[hb][nt][2] = 0.f; acc[hb][nt][3] = 0.f;
                }
            }
        }
        __syncwarp();

        // ---- GEMM2: K=128 (16 k-steps), N=128, M=32 ----
        #pragma unroll
        for (int k = 0; k < 16; k++) {
            uint32_t a0, a1, a2, a3, e0, e1, e2, e3;
            ldsm_x4(a0, a1, a2, a3, aA0 + k * 32);
            ldsm_x4(e0, e1, e2, e3, aA1 + k * 32);
            #pragma unroll
            for (int p = 0; p < 8; p++) {
                uint32_t b0, b1v, b2v, b3r;
                ldsm_x4(b0, b1v, b2v, b3r, bB2 + p * 8448 + k * 32);
                mma_tf32(acc[0][2 * p],     a0, a1, a2, a3, b0, b1v);
                mma_tf32(acc[0][2 * p + 1], a0, a1, a2, a3, b2v, b3r);
                mma_tf32(acc[1][2 * p],     e0, e1, e2, e3, b0, b1v);
                mma_tf32(acc[1][2 * p + 1], e0, e1, e2, e3, b2v, b3r);
            }
        }

        // ---- epilogue2: out = b3 + sum_n relu(C2 + b2)*W3 ----
        {
            float part[4] = {0.f, 0.f, 0.f, 0.f};
            #pragma unroll
            for (int nt = 0; nt < 16; nt++) {
                int h0 = nt * 8 + 2 * qc;
                float2 b2v = *(const float2*)(s + OFF_B2S + h0);
                float2 w3v = *(const float2*)(s + OFF_W3S + h0);
                #pragma unroll
                for (int hb = 0; hb < 2; hb++) {
                    part[hb * 2]     += fmaxf(acc[hb][nt][0] + b2v.x, 0.f) * w3v.x
                                      + fmaxf(acc[hb][nt][1] + b2v.y, 0.f) * w3v.y;
                    part[hb * 2 + 1] += fmaxf(acc[hb][nt][2] + b2v.x, 0.f) * w3v.x
                                      + fmaxf(acc[hb][nt][3] + b2v.y, 0.f) * w3v.y;
                }
            }
            #pragma unroll
            for (int q = 0; q < 4; q++) {
                part[q] += __shfl_xor_sync(0xffffffff, part[q], 1);
                part[q] += __shfl_xor_sync(0xffffffff, part[q], 2);
            }
            if (qc == 0) {
                size_t obase = ((size_t)(b * NN + i)) * NN + jt * 128 + m32;
                out[obase + qr]      = part[0] + b3v;
                out[obase + 8 + qr]  = part[1] + b3v;
                out[obase + 16 + qr] = part[2] + b3v;
                out[obase + 24 + qr] = part[3] + b3v;
            }
        }
    }
}

extern "C" void kernel_launch(void* const* d_in, const int* in_sizes, int n_in,
                              void* d_out, int out_size)
{
    const float* x  = (const float*)d_in[0];
    const float* y  = (const float*)d_in[1];
    const float* t  = (const float*)d_in[2];
    const float* W1 = (const float*)d_in[3];
    const float* b1 = (const float*)d_in[4];
    const float* W2 = (const float*)d_in[5];
    const float* b2 = (const float*)d_in[6];
    const float* W3 = (const float*)d_in[7];
    const float* b3 = (const float*)d_in[8];
    float* out = (float*)d_out;

    const int smem_bytes = SMEM_FLOATS * sizeof(float);
    cudaFuncSetAttribute(pairmlp_mma,
                         cudaFuncAttributeMaxDynamicSharedMemorySize, smem_bytes);
    pairmlp_mma<<<GRID, TPB, smem_bytes>>>(x, y, t, W1, b1, W2, b2, W3, b3, out);
}

// round 5
// speedup vs baseline: 2.2422x; 2.2422x over previous
#include <cuda_runtime.h>
#include <cuda_fp16.h>
#include <cstdint>

#define NN 512
#define GRID 148
#define TPB 256
#define PT 4096   // pair-tiles: 4 b x 4 jt x 256 i-pairs

// ---- SMEM byte offsets ----
#define OB_W1T 0        // fp16 [n=128][k=64]  stride 72 fp16 (144B)  -> 18432
#define OB_W2T 18432    // fp16 [n=128][h=128] stride 136 fp16 (272B) -> 34816
#define OB_DH0 53248    // fp16 [j=128][136] union diff/H (group 0)   -> 34816
#define OB_DH1 88064    // group 1
#define OB_YS  122880   // f32 [128][68]                              -> 34816
#define OB_TV  157696   // f32 [4][128]
#define OB_B2S 159744   // f32 [128]
#define OB_W3S 160256   // f32 [128]
#define SMEM_BYTES 160768

__device__ __forceinline__ uint32_t smem_u32(const void* p) {
    uint32_t a;
    asm("{ .reg .u64 t; cvta.to.shared.u64 t, %1; cvt.u32.u64 %0, t; }" : "=r"(a) : "l"(p));
    return a;
}
__device__ __forceinline__ uint32_t pack2(float e0, float e1) {
    __half2 h = __floats2half2_rn(e0, e1);     // .x (low) = e0
    return *(uint32_t*)&h;
}
__device__ __forceinline__ void ldsm_x4(uint32_t& r0, uint32_t& r1, uint32_t& r2, uint32_t& r3,
                                        uint32_t addr) {
    asm volatile("ldmatrix.sync.aligned.m8n8.x4.shared.b16 {%0,%1,%2,%3}, [%4];"
                 : "=r"(r0), "=r"(r1), "=r"(r2), "=r"(r3) : "r"(addr));
}
__device__ __forceinline__ void mma_f16(float* c, const uint32_t* a,
                                        uint32_t b0, uint32_t b1) {
    asm volatile("mma.sync.aligned.m16n8k16.row.col.f32.f16.f16.f32 "
                 "{%0,%1,%2,%3},{%4,%5,%6,%7},{%8,%9},{%0,%1,%2,%3};"
                 : "+f"(c[0]), "+f"(c[1]), "+f"(c[2]), "+f"(c[3])
                 : "r"(a[0]), "r"(a[1]), "r"(a[2]), "r"(a[3]), "r"(b0), "r"(b1));
}

__global__ void __launch_bounds__(TPB, 1)
pairmlp_f16(const float* __restrict__ x, const float* __restrict__ y,
            const float* __restrict__ t, const float* __restrict__ W1,
            const float* __restrict__ b1, const float* __restrict__ W2,
            const float* __restrict__ b2, const float* __restrict__ W3,
            const float* __restrict__ b3, float* __restrict__ out)
{
    extern __shared__ char sm[];
    float* ys  = (float*)(sm + OB_YS);
    float* tvs = (float*)(sm + OB_TV);
    float* b2s = (float*)(sm + OB_B2S);
    float* w3s = (float*)(sm + OB_W3S);
    __half* w1t = (__half*)(sm + OB_W1T);
    __half* w2t = (__half*)(sm + OB_W2T);

    const int tid = threadIdx.x;
    const int wid = tid >> 5;
    const int l   = tid & 31;
    const int grp = wid >> 2;          // which i of the pair
    const int m32 = (wid & 3) * 32;    // warp's 32 j-rows
    const uint32_t sb = smem_u32(sm);
    const uint32_t dhb = sb + (grp ? OB_DH1 : OB_DH0);

    // ---- one-time staging ----
    for (int idx = tid; idx < 64 * 128; idx += TPB) {
        int k = idx >> 7, n = idx & 127;
        w1t[n * 72 + k] = __float2half(W1[k * 128 + n]);
    }
    for (int idx = tid; idx < 128 * 128; idx += TPB) {
        int h = idx >> 7, n = idx & 127;
        w2t[n * 136 + h] = __float2half(W2[h * 128 + n]);
    }
    for (int idx = tid; idx < 4 * 128; idx += TPB) {
        int bb = idx >> 7, h = idx & 127;
        float sum = b1[h];
        #pragma unroll
        for (int d = 0; d < 32; d++) sum += t[bb * 32 + d] * W1[(64 + d) * 128 + h];
        tvs[idx] = sum;
    }
    if (tid < 128) { b2s[tid] = b2[tid]; w3s[tid] = W3[tid]; }
    const float b3v = b3[0];
    __syncthreads();

    // ---- per-lane ldmatrix addresses ----
    const int g2 = l >> 3, r = l & 7;
    // A (16x16 fp16): m0 rows0-7/k0-7, m1 rows8-15/k0-7, m2 rows0-7/k8-15, m3 rows8-15/k8-15
    const uint32_t aA = dhb + (uint32_t)(m32 + (g2 & 1) * 8 + r) * 272 + (uint32_t)(g2 >> 1) * 16;
    // B x4 = 2 n-tiles x k16: m0 n(2p)/k0-7, m1 n(2p)/k8-15, m2 n(2p+1)/k0-7, m3 n(2p+1)/k8-15
    const uint32_t bB1 = sb + OB_W1T + (uint32_t)((g2 >> 1) * 8 + r) * 144 + (uint32_t)(g2 & 1) * 16;
    const uint32_t bB2 = sb + OB_W2T + (uint32_t)((g2 >> 1) * 8 + r) * 272 + (uint32_t)(g2 & 1) * 16;

    const int qr = l >> 2, qc = l & 3;
    const int start = (PT * blockIdx.x) / GRID;
    const int end   = (PT * (blockIdx.x + 1)) / GRID;
    int cur_bjt = -1;

    for (int tau = start; tau < end; ++tau) {
        const int b  = tau >> 10;
        const int jt = (tau >> 8) & 3;
        const int q  = tau & 255;
        const int i  = q * 2 + grp;
        const int bjt = tau >> 8;

        if (bjt != cur_bjt) {
            __syncthreads();
            const float4* yg = (const float4*)(y + ((size_t)(b * NN + jt * 128)) * 64);
            for (int idx = tid; idx < 128 * 16; idx += TPB) {
                int rr = idx >> 4, gg = idx & 15;
                float4 v = yg[rr * 16 + gg];
                float* dst = ys + rr * 68 + gg * 4;
                dst[0] = v.x; dst[1] = v.y; dst[2] = v.z; dst[3] = v.w;
            }
            cur_bjt = bjt;
            __syncthreads();
        }

        // ---- diff^2 -> DH strip (fp16), rows m32..m32+31, k-chunk qc*16 ----
        {
            const float4* xg = (const float4*)(x + ((size_t)(b * NN + i)) * 64 + qc * 16);
            float4 xv[4];
            #pragma unroll
            for (int qq = 0; qq < 4; qq++) xv[qq] = xg[qq];
            #pragma unroll
            for (int rr = 0; rr < 4; rr++) {
                int row = m32 + qr + rr * 8;
                const float4* yrow = (const float4*)(ys + row * 68 + qc * 16);
                uint32_t base = dhb + (uint32_t)row * 272 + (uint32_t)qc * 32;
                uint32_t u[8];
                #pragma unroll
                for (int qq = 0; qq < 4; qq++) {
                    float4 yv = yrow[qq];
                    float d0 = xv[qq].x - yv.x, d1 = xv[qq].y - yv.y;
                    float d2 = xv[qq].z - yv.z, d3 = xv[qq].w - yv.w;
                    u[2 * qq]     = pack2(d0 * d0, d1 * d1);
                    u[2 * qq + 1] = pack2(d2 * d2, d3 * d3);
                }
                *(uint4*)(sm + (base - sb))      = make_uint4(u[0], u[1], u[2], u[3]);
                *(uint4*)(sm + (base - sb) + 16) = make_uint4(u[4], u[5], u[6], u[7]);
            }
        }
        __syncwarp();

        // ---- load all GEMM1 A fragments (diff) into registers ----
        uint32_t a1[2][4][4];
        #pragma unroll
        for (int mb = 0; mb < 2; mb++)
            #pragma unroll
            for (int ks = 0; ks < 4; ks++)
                ldsm_x4(a1[mb][ks][0], a1[mb][ks][1], a1[mb][ks][2], a1[mb][ks][3],
                        aA + (uint32_t)mb * (16 * 272) + (uint32_t)ks * 32);
        __syncwarp();

        // ---- GEMM1 + epilogue1, two n-halves (h 0-63, 64-127) ----
        #pragma unroll
        for (int hf = 0; hf < 2; hf++) {
            float acc[2][8][4];
            #pragma unroll
            for (int mb = 0; mb < 2; mb++)
                #pragma unroll
                for (int nt = 0; nt < 8; nt++)
                    #pragma unroll
                    for (int c = 0; c < 4; c++) acc[mb][nt][c] = 0.f;

            const uint32_t bbase = bB1 + (uint32_t)hf * (64 * 144);
            #pragma unroll
            for (int ks = 0; ks < 4; ks++) {
                #pragma unroll
                for (int p = 0; p < 4; p++) {
                    uint32_t b0, b1v, b2v, b3r;
                    ldsm_x4(b0, b1v, b2v, b3r, bbase + (uint32_t)p * (16 * 144) + (uint32_t)ks * 32);
                    mma_f16(acc[0][2 * p],     a1[0][ks], b0, b1v);
                    mma_f16(acc[0][2 * p + 1], a1[0][ks], b2v, b3r);
                    mma_f16(acc[1][2 * p],     a1[1][ks], b0, b1v);
                    mma_f16(acc[1][2 * p + 1], a1[1][ks], b2v, b3r);
                }
            }
            // epilogue1: H[j][h] = fp16(relu(acc + tv)); safe: a1 already in regs
            const float* tvb = tvs + b * 128 + hf * 64;
            #pragma unroll
            for (int nt = 0; nt < 8; nt++) {
                int h0 = nt * 8 + 2 * qc;
                float2 tvv = *(const float2*)(tvb + h0);
                uint32_t hoff = (uint32_t)(hf * 64 + h0) * 2;
                #pragma unroll
                for (int mb = 0; mb < 2; mb++) {
                    uint32_t rb = dhb + (uint32_t)(m32 + mb * 16 + qr) * 272 + hoff;
                    *(uint32_t*)(sm + (rb - sb)) =
                        pack2(fmaxf(acc[mb][nt][0] + tvv.x, 0.f),
                              fmaxf(acc[mb][nt][1] + tvv.y, 0.f));
                    *(uint32_t*)(sm + (rb - sb) + 8 * 272) =
                        pack2(fmaxf(acc[mb][nt][2] + tvv.x, 0.f),
                              fmaxf(acc[mb][nt][3] + tvv.y, 0.f));
                }
            }
        }
        __syncwarp();

        // ---- load all GEMM2 A fragments (H) into registers ----
        uint32_t a2[2][8][4];
        #pragma unroll
        for (int mb = 0; mb < 2; mb++)
            #pragma unroll
            for (int ks = 0; ks < 8; ks++)
                ldsm_x4(a2[mb][ks][0], a2[mb][ks][1], a2[mb][ks][2], a2[mb][ks][3],
                        aA + (uint32_t)mb * (16 * 272) + (uint32_t)ks * 32);

        // ---- GEMM2 + epilogue2, two n-halves ----
        float part[4] = {0.f, 0.f, 0.f, 0.f};
        #pragma unroll
        for (int hf = 0; hf < 2; hf++) {
            float acc[2][8][4];
            #pragma unroll
            for (int mb = 0; mb < 2; mb++)
                #pragma unroll
                for (int nt = 0; nt < 8; nt++)
                    #pragma unroll
                    for (int c = 0; c < 4; c++) acc[mb][nt][c] = 0.f;

            const uint32_t bbase = bB2 + (uint32_t)hf * (64 * 272);
            #pragma unroll
            for (int ks = 0; ks < 8; ks++) {
                #pragma unroll
                for (int p = 0; p < 4; p++) {
                    uint32_t b0, b1v, b2v, b3r;
                    ldsm_x4(b0, b1v, b2v, b3r, bbase + (uint32_t)p * (16 * 272) + (uint32_t)ks * 32);
                    mma_f16(acc[0][2 * p],     a2[0][ks], b0, b1v);
                    mma_f16(acc[0][2 * p + 1], a2[0][ks], b2v, b3r);
                    mma_f16(acc[1][2 * p],     a2[1][ks], b0, b1v);
                    mma_f16(acc[1][2 * p + 1], a2[1][ks], b2v, b3r);
                }
            }
            const float* b2b = b2s + hf * 64;
            const float* w3b = w3s + hf * 64;
            #pragma unroll
            for (int nt = 0; nt < 8; nt++) {
                int h0 = nt * 8 + 2 * qc;
                float2 b2v = *(const float2*)(b2b + h0);
                float2 w3v = *(const float2*)(w3b + h0);
                #pragma unroll
                for (int mb = 0; mb < 2; mb++) {
                    part[mb * 2]     += fmaxf(acc[mb][nt][0] + b2v.x, 0.f) * w3v.x
                                      + fmaxf(acc[mb][nt][1] + b2v.y, 0.f) * w3v.y;
                    part[mb * 2 + 1] += fmaxf(acc[mb][nt][2] + b2v.x, 0.f) * w3v.x
                                      + fmaxf(acc[mb][nt][3] + b2v.y, 0.f) * w3v.y;
                }
            }
        }

        #pragma unroll
        for (int p = 0; p < 4; p++) {
            part[p] += __shfl_xor_sync(0xffffffff, part[p], 1);
            part[p] += __shfl_xor_sync(0xffffffff, part[p], 2);
        }
        if (qc == 0) {
            size_t obase = ((size_t)(b * NN + i)) * NN + jt * 128 + m32;
            out[obase + qr]      = part[0] + b3v;
            out[obase + 8 + qr]  = part[1] + b3v;
            out[obase + 16 + qr] = part[2] + b3v;
            out[obase + 24 + qr] = part[3] + b3v;
        }
    }
}

extern "C" void kernel_launch(void* const* d_in, const int* in_sizes, int n_in,
                              void* d_out, int out_size)
{
    const float* x  = (const float*)d_in[0];
    const float* y  = (const float*)d_in[1];
    const float* t  = (const float*)d_in[2];
    const float* W1 = (const float*)d_in[3];
    const float* b1 = (const float*)d_in[4];
    const float* W2 = (const float*)d_in[5];
    const float* b2 = (const float*)d_in[6];
    const float* W3 = (const float*)d_in[7];
    const float* b3 = (const float*)d_in[8];
    float* out = (float*)d_out;

    cudaFuncSetAttribute(pairmlp_f16,
                         cudaFuncAttributeMaxDynamicSharedMemorySize, SMEM_BYTES);
    pairmlp_f16<<<GRID, TPB, SMEM_BYTES>>>(x, y, t, W1, b1, W2, b2, W3, b3, out);
}

// round 6
// speedup vs baseline: 2.2755x; 1.0149x over previous
#include <cuda_runtime.h>
#include <cuda_fp16.h>
#include <cstdint>

#define NN 512
#define GRID 148
#define TPB 384
#define NT 2736          // 4 b x 4 jt x 171 i-triples

// ---- SMEM byte offsets ----
#define OB_W1T 0        // fp16 [n=128][k=64]  stride 72 fp16 (144B)  -> 18432
#define OB_W2T 18432    // fp16 [n=128][h=128] stride 136 fp16 (272B) -> 34816
#define OB_DH0 53248    // fp16 [j=128][136] union diff/H (group 0)
#define OB_DH1 88064
#define OB_DH2 122880
#define OB_YS  157696   // f32 [128][68]
#define OB_TV  192512   // f32 [4][128]
#define OB_B2S 194560
#define OB_W3S 195072
#define SMEM_BYTES 195584

__device__ __forceinline__ uint32_t smem_u32(const void* p) {
    uint32_t a;
    asm("{ .reg .u64 t; cvta.to.shared.u64 t, %1; cvt.u32.u64 %0, t; }" : "=r"(a) : "l"(p));
    return a;
}
__device__ __forceinline__ uint32_t pack2(float e0, float e1) {
    __half2 h = __floats2half2_rn(e0, e1);
    return *(uint32_t*)&h;
}
__device__ __forceinline__ void ldsm_x4(uint32_t& r0, uint32_t& r1, uint32_t& r2, uint32_t& r3,
                                        uint32_t addr) {
    asm volatile("ldmatrix.sync.aligned.m8n8.x4.shared.b16 {%0,%1,%2,%3}, [%4];"
                 : "=r"(r0), "=r"(r1), "=r"(r2), "=r"(r3) : "r"(addr));
}
__device__ __forceinline__ void mma_f16(float* c, const uint32_t* a,
                                        uint32_t b0, uint32_t b1) {
    asm volatile("mma.sync.aligned.m16n8k16.row.col.f32.f16.f16.f32 "
                 "{%0,%1,%2,%3},{%4,%5,%6,%7},{%8,%9},{%0,%1,%2,%3};"
                 : "+f"(c[0]), "+f"(c[1]), "+f"(c[2]), "+f"(c[3])
                 : "r"(a[0]), "r"(a[1]), "r"(a[2]), "r"(a[3]), "r"(b0), "r"(b1));
}

__global__ void __launch_bounds__(TPB, 1)
pairmlp_f16(const float* __restrict__ x, const float* __restrict__ y,
            const float* __restrict__ t, const float* __restrict__ W1,
            const float* __restrict__ b1, const float* __restrict__ W2,
            const float* __restrict__ b2, const float* __restrict__ W3,
            const float* __restrict__ b3, float* __restrict__ out)
{
    extern __shared__ char sm[];
    float* ys  = (float*)(sm + OB_YS);
    float* tvs = (float*)(sm + OB_TV);
    float* b2s = (float*)(sm + OB_B2S);
    float* w3s = (float*)(sm + OB_W3S);
    __half* w1t = (__half*)(sm + OB_W1T);
    __half* w2t = (__half*)(sm + OB_W2T);

    const int tid = threadIdx.x;
    const int wid = tid >> 5;
    const int l   = tid & 31;
    const int grp = wid >> 2;          // 0..2: which i of the triple
    const int m32 = (wid & 3) * 32;    // warp's 32 j-rows
    const uint32_t sb = smem_u32(sm);
    const uint32_t dhb = sb + OB_DH0 + (uint32_t)grp * 34816u;

    // ---- one-time staging ----
    for (int idx = tid; idx < 64 * 128; idx += TPB) {
        int k = idx >> 7, n = idx & 127;
        w1t[n * 72 + k] = __float2half(W1[k * 128 + n]);
    }
    for (int idx = tid; idx < 128 * 128; idx += TPB) {
        int h = idx >> 7, n = idx & 127;
        w2t[n * 136 + h] = __float2half(W2[h * 128 + n]);
    }
    for (int idx = tid; idx < 4 * 128; idx += TPB) {
        int bb = idx >> 7, h = idx & 127;
        float sum = b1[h];
        #pragma unroll
        for (int d = 0; d < 32; d++) sum += t[bb * 32 + d] * W1[(64 + d) * 128 + h];
        tvs[idx] = sum;
    }
    if (tid < 128) { b2s[tid] = b2[tid]; w3s[tid] = W3[tid]; }
    const float b3v = b3[0];
    __syncthreads();

    // ---- per-lane ldmatrix addresses ----
    const int g2 = l >> 3, r = l & 7;
    const uint32_t aA = dhb + (uint32_t)(m32 + (g2 & 1) * 8 + r) * 272 + (uint32_t)(g2 >> 1) * 16;
    const uint32_t bB1 = sb + OB_W1T + (uint32_t)((g2 >> 1) * 8 + r) * 144 + (uint32_t)(g2 & 1) * 16;
    const uint32_t bB2 = sb + OB_W2T + (uint32_t)((g2 >> 1) * 8 + r) * 272 + (uint32_t)(g2 & 1) * 16;

    const int qr = l >> 2, qc = l & 3;
    const int start = (NT * blockIdx.x) / GRID;
    const int end   = (NT * (blockIdx.x + 1)) / GRID;
    int cur_bjt = -1;

    for (int tau = start; tau < end; ++tau) {
        const int bjt = tau / 171;         // 0..15
        const int q   = tau - bjt * 171;   // 0..170
        const int b   = bjt >> 2;
        const int jt  = bjt & 3;
        const int i   = q * 3 + grp;
        const int ild = (i < NN) ? i : (NN - 1);   // clamp loads for tail triple

        if (bjt != cur_bjt) {
            __syncthreads();
            const float4* yg = (const float4*)(y + ((size_t)(b * NN + jt * 128)) * 64);
            for (int idx = tid; idx < 128 * 16; idx += TPB) {
                int rr = idx >> 4, gg = idx & 15;
                float4 v = yg[rr * 16 + gg];
                float* dst = ys + rr * 68 + gg * 4;
                dst[0] = v.x; dst[1] = v.y; dst[2] = v.z; dst[3] = v.w;
            }
            cur_bjt = bjt;
            __syncthreads();
        }

        // ---- diff^2 -> DH strip (fp16), rows m32..m32+31, k-chunk qc*16 ----
        {
            const float4* xg = (const float4*)(x + ((size_t)(b * NN + ild)) * 64 + qc * 16);
            float4 xv[4];
            #pragma unroll
            for (int qq = 0; qq < 4; qq++) xv[qq] = xg[qq];
            #pragma unroll
            for (int rr = 0; rr < 4; rr++) {
                int row = m32 + qr + rr * 8;
                const float4* yrow = (const float4*)(ys + row * 68 + qc * 16);
                uint32_t base = dhb - sb + (uint32_t)row * 272 + (uint32_t)qc * 32;
                uint32_t u[8];
                #pragma unroll
                for (int qq = 0; qq < 4; qq++) {
                    float4 yv = yrow[qq];
                    float d0 = xv[qq].x - yv.x, d1 = xv[qq].y - yv.y;
                    float d2 = xv[qq].z - yv.z, d3 = xv[qq].w - yv.w;
                    u[2 * qq]     = pack2(d0 * d0, d1 * d1);
                    u[2 * qq + 1] = pack2(d2 * d2, d3 * d3);
                }
                *(uint4*)(sm + base)      = make_uint4(u[0], u[1], u[2], u[3]);
                *(uint4*)(sm + base + 16) = make_uint4(u[4], u[5], u[6], u[7]);
            }
        }
        __syncwarp();

        // ---- preload GEMM1 A fragments (diff) -- needed across both n-halves
        uint32_t a1[2][4][4];
        #pragma unroll
        for (int mb = 0; mb < 2; mb++)
            #pragma unroll
            for (int ks = 0; ks < 4; ks++)
                ldsm_x4(a1[mb][ks][0], a1[mb][ks][1], a1[mb][ks][2], a1[mb][ks][3],
                        aA + (uint32_t)mb * (16 * 272) + (uint32_t)ks * 32);
        __syncwarp();

        // ---- GEMM1 + epilogue1, two n-halves ----
        #pragma unroll
        for (int hf = 0; hf < 2; hf++) {
            float acc[2][8][4];
            #pragma unroll
            for (int mb = 0; mb < 2; mb++)
                #pragma unroll
                for (int nt = 0; nt < 8; nt++)
                    #pragma unroll
                    for (int c = 0; c < 4; c++) acc[mb][nt][c] = 0.f;

            const uint32_t bbase = bB1 + (uint32_t)hf * (64 * 144);
            #pragma unroll
            for (int ks = 0; ks < 4; ks++) {
                #pragma unroll
                for (int p = 0; p < 4; p++) {
                    uint32_t b0, b1v, b2v, b3r;
                    ldsm_x4(b0, b1v, b2v, b3r, bbase + (uint32_t)p * (16 * 144) + (uint32_t)ks * 32);
                    mma_f16(acc[0][2 * p],     a1[0][ks], b0, b1v);
                    mma_f16(acc[0][2 * p + 1], a1[0][ks], b2v, b3r);
                    mma_f16(acc[1][2 * p],     a1[1][ks], b0, b1v);
                    mma_f16(acc[1][2 * p + 1], a1[1][ks], b2v, b3r);
                }
            }
            const float* tvb = tvs + b * 128 + hf * 64;
            #pragma unroll
            for (int nt = 0; nt < 8; nt++) {
                int h0 = nt * 8 + 2 * qc;
                float2 tvv = *(const float2*)(tvb + h0);
                uint32_t hoff = (uint32_t)(hf * 64 + h0) * 2;
                #pragma unroll
                for (int mb = 0; mb < 2; mb++) {
                    uint32_t rb = dhb - sb + (uint32_t)(m32 + mb * 16 + qr) * 272 + hoff;
                    *(uint32_t*)(sm + rb) =
                        pack2(fmaxf(acc[mb][nt][0] + tvv.x, 0.f),
                              fmaxf(acc[mb][nt][1] + tvv.y, 0.f));
                    *(uint32_t*)(sm + rb + 8 * 272) =
                        pack2(fmaxf(acc[mb][nt][2] + tvv.x, 0.f),
                              fmaxf(acc[mb][nt][3] + tvv.y, 0.f));
                }
            }
        }
        __syncwarp();

        // ---- GEMM2 + epilogue2, hf-outer, A reloaded per k-step (reg cap) ----
        float part[4] = {0.f, 0.f, 0.f, 0.f};
        #pragma unroll
        for (int hf = 0; hf < 2; hf++) {
            float acc[2][8][4];
            #pragma unroll
            for (int mb = 0; mb < 2; mb++)
                #pragma unroll
                for (int nt = 0; nt < 8; nt++)
                    #pragma unroll
                    for (int c = 0; c < 4; c++) acc[mb][nt][c] = 0.f;

            const uint32_t bbase = bB2 + (uint32_t)hf * (64 * 272);
            #pragma unroll
            for (int ks = 0; ks < 8; ks++) {
                uint32_t af[2][4];
                ldsm_x4(af[0][0], af[0][1], af[0][2], af[0][3], aA + (uint32_t)ks * 32);
                ldsm_x4(af[1][0], af[1][1], af[1][2], af[1][3],
                        aA + (16 * 272) + (uint32_t)ks * 32);
                #pragma unroll
                for (int p = 0; p < 4; p++) {
                    uint32_t b0, b1v, b2v, b3r;
                    ldsm_x4(b0, b1v, b2v, b3r, bbase + (uint32_t)p * (16 * 272) + (uint32_t)ks * 32);
                    mma_f16(acc[0][2 * p],     af[0], b0, b1v);
                    mma_f16(acc[0][2 * p + 1], af[0], b2v, b3r);
                    mma_f16(acc[1][2 * p],     af[1], b0, b1v);
                    mma_f16(acc[1][2 * p + 1], af[1], b2v, b3r);
                }
            }
            const float* b2b = b2s + hf * 64;
            const float* w3b = w3s + hf * 64;
            #pragma unroll
            for (int nt = 0; nt < 8; nt++) {
                int h0 = nt * 8 + 2 * qc;
                float2 b2v = *(const float2*)(b2b + h0);
                float2 w3v = *(const float2*)(w3b + h0);
                #pragma unroll
                for (int mb = 0; mb < 2; mb++) {
                    part[mb * 2]     += fmaxf(acc[mb][nt][0] + b2v.x, 0.f) * w3v.x
                                      + fmaxf(acc[mb][nt][1] + b2v.y, 0.f) * w3v.y;
                    part[mb * 2 + 1] += fmaxf(acc[mb][nt][2] + b2v.x, 0.f) * w3v.x
                                      + fmaxf(acc[mb][nt][3] + b2v.y, 0.f) * w3v.y;
                }
            }
        }

        #pragma unroll
        for (int p = 0; p < 4; p++) {
            part[p] += __shfl_xor_sync(0xffffffff, part[p], 1);
            part[p] += __shfl_xor_sync(0xffffffff, part[p], 2);
        }
        if (qc == 0 && i < NN) {
            size_t obase = ((size_t)(b * NN + i)) * NN + jt * 128 + m32;
            out[obase + qr]      = part[0] + b3v;
            out[obase + 8 + qr]  = part[1] + b3v;
            out[obase + 16 + qr] = part[2] + b3v;
            out[obase + 24 + qr] = part[3] + b3v;
        }
    }
}

extern "C" void kernel_launch(void* const* d_in, const int* in_sizes, int n_in,
                              void* d_out, int out_size)
{
    const float* x  = (const float*)d_in[0];
    const float* y  = (const float*)d_in[1];
    const float* t  = (const float*)d_in[2];
    const float* W1 = (const float*)d_in[3];
    const float* b1 = (const float*)d_in[4];
    const float* W2 = (const float*)d_in[5];
    const float* b2 = (const float*)d_in[6];
    const float* W3 = (const float*)d_in[7];
    const float* b3 = (const float*)d_in[8];
    float* out = (float*)d_out;

    cudaFuncSetAttribute(pairmlp_f16,
                         cudaFuncAttributeMaxDynamicSharedMemorySize, SMEM_BYTES);
    pairmlp_f16<<<GRID, TPB, SMEM_BYTES>>>(x, y, t, W1, b1, W2, b2, W3, b3, out);
}

// round 7
// speedup vs baseline: 2.2992x; 1.0104x over previous
#include <cuda_runtime.h>
#include <cuda_fp16.h>
#include <cstdint>

#define NN 512
#define GRID 148
#define TPB 256
#define PT 4096   // 4 b x 4 jt x 256 i-pairs

// ---- SMEM byte offsets ----
#define OB_W1T 0        // fp16 [n=128][k=64]  stride 72 fp16 (144B)  -> 18432
#define OB_W2T 18432    // fp16 [n=128][h=128] stride 136 fp16 (272B) -> 34816
#define OB_DH0 53248    // fp16 diff [j=128][72] stride 144B (group 0) -> 18432
#define OB_DH1 71680    // group 1
#define OB_YS  90112    // f32 [128][68] -> 34816
#define OB_TV  124928   // f32 [4][128]
#define OB_B2S 126976   // f32 [128]
#define OB_W3S 127488   // f32 [128]
#define SMEM_BYTES 128000

__device__ __forceinline__ uint32_t smem_u32(const void* p) {
    uint32_t a;
    asm("{ .reg .u64 t; cvta.to.shared.u64 t, %1; cvt.u32.u64 %0, t; }" : "=r"(a) : "l"(p));
    return a;
}
__device__ __forceinline__ uint32_t pack2(float e0, float e1) {
    __half2 h = __floats2half2_rn(e0, e1);
    return *(uint32_t*)&h;
}
__device__ __forceinline__ void ldsm_x4(uint32_t& r0, uint32_t& r1, uint32_t& r2, uint32_t& r3,
                                        uint32_t addr) {
    asm volatile("ldmatrix.sync.aligned.m8n8.x4.shared.b16 {%0,%1,%2,%3}, [%4];"
                 : "=r"(r0), "=r"(r1), "=r"(r2), "=r"(r3) : "r"(addr));
}
__device__ __forceinline__ void mma_f16(float* c, const uint32_t* a,
                                        uint32_t b0, uint32_t b1) {
    asm volatile("mma.sync.aligned.m16n8k16.row.col.f32.f16.f16.f32 "
                 "{%0,%1,%2,%3},{%4,%5,%6,%7},{%8,%9},{%0,%1,%2,%3};"
                 : "+f"(c[0]), "+f"(c[1]), "+f"(c[2]), "+f"(c[3])
                 : "r"(a[0]), "r"(a[1]), "r"(a[2]), "r"(a[3]), "r"(b0), "r"(b1));
}

__global__ void __launch_bounds__(TPB, 1)
pairmlp_f16(const float* __restrict__ x, const float* __restrict__ y,
            const float* __restrict__ t, const float* __restrict__ W1,
            const float* __restrict__ b1, const float* __restrict__ W2,
            const float* __restrict__ b2, const float* __restrict__ W3,
            const float* __restrict__ b3, float* __restrict__ out)
{
    extern __shared__ char sm[];
    float* ys  = (float*)(sm + OB_YS);
    float* tvs = (float*)(sm + OB_TV);
    float* b2s = (float*)(sm + OB_B2S);
    float* w3s = (float*)(sm + OB_W3S);
    __half* w1t = (__half*)(sm + OB_W1T);
    __half* w2t = (__half*)(sm + OB_W2T);

    const int tid = threadIdx.x;
    const int wid = tid >> 5;
    const int l   = tid & 31;
    const int grp = wid >> 2;          // 0/1: which i of the pair
    const int m32 = (wid & 3) * 32;    // warp's 32 j-rows
    const uint32_t sb = smem_u32(sm);
    const uint32_t dhb = sb + (grp ? OB_DH1 : OB_DH0);

    // ---- one-time staging ----
    for (int idx = tid; idx < 64 * 128; idx += TPB) {
        int k = idx >> 7, n = idx & 127;
        w1t[n * 72 + k] = __float2half(W1[k * 128 + n]);
    }
    for (int idx = tid; idx < 128 * 128; idx += TPB) {
        int h = idx >> 7, n = idx & 127;
        w2t[n * 136 + h] = __float2half(W2[h * 128 + n]);
    }
    for (int idx = tid; idx < 4 * 128; idx += TPB) {
        int bb = idx >> 7, h = idx & 127;
        float sum = b1[h];
        #pragma unroll
        for (int d = 0; d < 32; d++) sum += t[bb * 32 + d] * W1[(64 + d) * 128 + h];
        tvs[idx] = sum;
    }
    if (tid < 128) { b2s[tid] = b2[tid]; w3s[tid] = W3[tid]; }
    const float b3v = b3[0];
    __syncthreads();

    // ---- per-lane ldmatrix addresses ----
    const int g2 = l >> 3, r = l & 7;
    // A1 (diff, 16x16 fp16, row stride 144B)
    const uint32_t aA = dhb + (uint32_t)(m32 + (g2 & 1) * 8 + r) * 144 + (uint32_t)(g2 >> 1) * 16;
    // B x4 = 2 n8-tiles x k16
    const uint32_t bB1 = sb + OB_W1T + (uint32_t)((g2 >> 1) * 8 + r) * 144 + (uint32_t)(g2 & 1) * 16;
    const uint32_t bB2 = sb + OB_W2T + (uint32_t)((g2 >> 1) * 8 + r) * 272 + (uint32_t)(g2 & 1) * 16;

    const int qr = l >> 2, qc = l & 3;
    const int start = (PT * blockIdx.x) / GRID;
    const int end   = (PT * (blockIdx.x + 1)) / GRID;
    int cur_bjt = -1;

    for (int tau = start; tau < end; ++tau) {
        const int b  = tau >> 10;
        const int jt = (tau >> 8) & 3;
        const int q  = tau & 255;
        const int i  = q * 2 + grp;
        const int bjt = tau >> 8;

        if (bjt != cur_bjt) {
            __syncthreads();
            const float4* yg = (const float4*)(y + ((size_t)(b * NN + jt * 128)) * 64);
            for (int idx = tid; idx < 128 * 16; idx += TPB) {
                int rr = idx >> 4, gg = idx & 15;
                float4 v = yg[rr * 16 + gg];
                float* dst = ys + rr * 68 + gg * 4;
                dst[0] = v.x; dst[1] = v.y; dst[2] = v.z; dst[3] = v.w;
            }
            cur_bjt = bjt;
            __syncthreads();
        }

        // ---- diff^2 -> DH strip (fp16), rows m32..m32+31, k-chunk qc*16 ----
        {
            const float4* xg = (const float4*)(x + ((size_t)(b * NN + i)) * 64 + qc * 16);
            float4 xv[4];
            #pragma unroll
            for (int qq = 0; qq < 4; qq++) xv[qq] = xg[qq];
            #pragma unroll
            for (int rr = 0; rr < 4; rr++) {
                int row = m32 + qr + rr * 8;
                const float4* yrow = (const float4*)(ys + row * 68 + qc * 16);
                uint32_t base = dhb - sb + (uint32_t)row * 144 + (uint32_t)qc * 32;
                uint32_t u[8];
                #pragma unroll
                for (int qq = 0; qq < 4; qq++) {
                    float4 yv = yrow[qq];
                    float d0 = xv[qq].x - yv.x, d1 = xv[qq].y - yv.y;
                    float d2 = xv[qq].z - yv.z, d3 = xv[qq].w - yv.w;
                    u[2 * qq]     = pack2(d0 * d0, d1 * d1);
                    u[2 * qq + 1] = pack2(d2 * d2, d3 * d3);
                }
                *(uint4*)(sm + base)      = make_uint4(u[0], u[1], u[2], u[3]);
                *(uint4*)(sm + base + 16) = make_uint4(u[4], u[5], u[6], u[7]);
            }
        }
        __syncwarp();

        // ---- preload GEMM1 A fragments (diff) ----
        uint32_t a1[2][4][4];
        #pragma unroll
        for (int mb = 0; mb < 2; mb++)
            #pragma unroll
            for (int ks = 0; ks < 4; ks++)
                ldsm_x4(a1[mb][ks][0], a1[mb][ks][1], a1[mb][ks][2], a1[mb][ks][3],
                        aA + (uint32_t)mb * (16 * 144) + (uint32_t)ks * 32);

        // ---- GEMM1: full N=128, M=32, K=64 ----
        float acc[2][16][4];
        #pragma unroll
        for (int mb = 0; mb < 2; mb++)
            #pragma unroll
            for (int nt = 0; nt < 16; nt++)
                #pragma unroll
                for (int c = 0; c < 4; c++) acc[mb][nt][c] = 0.f;

        #pragma unroll
        for (int ks = 0; ks < 4; ks++) {
            #pragma unroll
            for (int p = 0; p < 8; p++) {
                uint32_t b0, b1v, b2v, b3r;
                ldsm_x4(b0, b1v, b2v, b3r, bB1 + (uint32_t)p * (16 * 144) + (uint32_t)ks * 32);
                mma_f16(acc[0][2 * p],     a1[0][ks], b0, b1v);
                mma_f16(acc[0][2 * p + 1], a1[0][ks], b2v, b3r);
                mma_f16(acc[1][2 * p],     a1[1][ks], b0, b1v);
                mma_f16(acc[1][2 * p + 1], a1[1][ks], b2v, b3r);
            }
        }

        // ---- epilogue1 IN REGISTERS: af = GEMM2 A fragments = relu(C1+tv) ----
        // C(m16n8) frag -> A(m16k16) frag: a0=pack(c0,c1)|nt=2ks, a1=pack(c2,c3)|nt=2ks,
        //                                  a2=pack(c0,c1)|nt=2ks+1, a3=pack(c2,c3)|nt=2ks+1
        uint32_t af[2][8][4];
        {
            const float* tvb = tvs + b * 128;
            #pragma unroll
            for (int ks = 0; ks < 8; ks++) {
                float2 tv0 = *(const float2*)(tvb + (2 * ks) * 8 + 2 * qc);
                float2 tv1 = *(const float2*)(tvb + (2 * ks + 1) * 8 + 2 * qc);
                #pragma unroll
                for (int mb = 0; mb < 2; mb++) {
                    af[mb][ks][0] = pack2(fmaxf(acc[mb][2 * ks][0] + tv0.x, 0.f),
                                          fmaxf(acc[mb][2 * ks][1] + tv0.y, 0.f));
                    af[mb][ks][1] = pack2(fmaxf(acc[mb][2 * ks][2] + tv0.x, 0.f),
                                          fmaxf(acc[mb][2 * ks][3] + tv0.y, 0.f));
                    af[mb][ks][2] = pack2(fmaxf(acc[mb][2 * ks + 1][0] + tv1.x, 0.f),
                                          fmaxf(acc[mb][2 * ks + 1][1] + tv1.y, 0.f));
                    af[mb][ks][3] = pack2(fmaxf(acc[mb][2 * ks + 1][2] + tv1.x, 0.f),
                                          fmaxf(acc[mb][2 * ks + 1][3] + tv1.y, 0.f));
                }
            }
        }

        // ---- GEMM2: M=32, N=128, K=128; A from registers, B from SMEM ----
        #pragma unroll
        for (int mb = 0; mb < 2; mb++)
            #pragma unroll
            for (int nt = 0; nt < 16; nt++)
                #pragma unroll
                for (int c = 0; c < 4; c++) acc[mb][nt][c] = 0.f;

        #pragma unroll
        for (int ks = 0; ks < 8; ks++) {
            #pragma unroll
            for (int p = 0; p < 8; p++) {
                uint32_t b0, b1v, b2v, b3r;
                ldsm_x4(b0, b1v, b2v, b3r, bB2 + (uint32_t)p * (16 * 272) + (uint32_t)ks * 32);
                mma_f16(acc[0][2 * p],     af[0][ks], b0, b1v);
                mma_f16(acc[0][2 * p + 1], af[0][ks], b2v, b3r);
                mma_f16(acc[1][2 * p],     af[1][ks], b0, b1v);
                mma_f16(acc[1][2 * p + 1], af[1][ks], b2v, b3r);
            }
        }

        // ---- epilogue2: out = b3 + sum_n relu(C2 + b2)*W3 ----
        {
            float part[4] = {0.f, 0.f, 0.f, 0.f};
            #pragma unroll
            for (int nt = 0; nt < 16; nt++) {
                int h0 = nt * 8 + 2 * qc;
                float2 b2v = *(const float2*)(b2s + h0);
                float2 w3v = *(const float2*)(w3s + h0);
                #pragma unroll
                for (int mb = 0; mb < 2; mb++) {
                    part[mb * 2]     += fmaxf(acc[mb][nt][0] + b2v.x, 0.f) * w3v.x
                                      + fmaxf(acc[mb][nt][1] + b2v.y, 0.f) * w3v.y;
                    part[mb * 2 + 1] += fmaxf(acc[mb][nt][2] + b2v.x, 0.f) * w3v.x
                                      + fmaxf(acc[mb][nt][3] + b2v.y, 0.f) * w3v.y;
                }
            }
            #pragma unroll
            for (int p = 0; p < 4; p++) {
                part[p] += __shfl_xor_sync(0xffffffff, part[p], 1);
                part[p] += __shfl_xor_sync(0xffffffff, part[p], 2);
            }
            if (qc == 0) {
                size_t obase = ((size_t)(b * NN + i)) * NN + jt * 128 + m32;
                out[obase + qr]      = part[0] + b3v;
                out[obase + 8 + qr]  = part[1] + b3v;
                out[obase + 16 + qr] = part[2] + b3v;
                out[obase + 24 + qr] = part[3] + b3v;
            }
        }
    }
}

extern "C" void kernel_launch(void* const* d_in, const int* in_sizes, int n_in,
                              void* d_out, int out_size)
{
    const float* x  = (const float*)d_in[0];
    const float* y  = (const float*)d_in[1];
    const float* t  = (const float*)d_in[2];
    const float* W1 = (const float*)d_in[3];
    const float* b1 = (const float*)d_in[4];
    const float* W2 = (const float*)d_in[5];
    const float* b2 = (const float*)d_in[6];
    const float* W3 = (const float*)d_in[7];
    const float* b3 = (const float*)d_in[8];
    float* out = (float*)d_out;

    cudaFuncSetAttribute(pairmlp_f16,
                         cudaFuncAttributeMaxDynamicSharedMemorySize, SMEM_BYTES);
    pairmlp_f16<<<GRID, TPB, SMEM_BYTES>>>(x, y, t, W1, b1, W2, b2, W3, b3, out);
}

// round 8
// speedup vs baseline: 2.3476x; 1.0210x over previous
#include <cuda_runtime.h>
#include <cuda_fp16.h>
#include <cstdint>

#define NN 512
#define GRID 148
#define TPB 512
#define PT 4096   // 4 b x 4 jt x 256 i-pairs

// ---- SMEM byte offsets ----
#define OB_W1T 0        // fp16 [n=128][k=64]  stride 72 fp16 (144B)  -> 18432
#define OB_W2T 18432    // fp16 [n=128][h=128] stride 136 fp16 (272B) -> 34816
#define OB_DH0 53248    // fp16 diff [j=128][72] stride 144B (group 0) -> 18432
#define OB_DH1 71680    // group 1
#define OB_YS  90112    // f32 [128][68] -> 34816
#define OB_TV2 124928   // half2-packed tv [4][64] u32 -> 4096
#define OB_B2S 129024   // f32 [128]
#define OB_W3S 129536   // f32 [128]
#define SMEM_BYTES 130048

__device__ __forceinline__ uint32_t smem_u32(const void* p) {
    uint32_t a;
    asm("{ .reg .u64 t; cvta.to.shared.u64 t, %1; cvt.u32.u64 %0, t; }" : "=r"(a) : "l"(p));
    return a;
}
__device__ __forceinline__ uint32_t pack2(float e0, float e1) {
    __half2 h = __floats2half2_rn(e0, e1);
    return *(uint32_t*)&h;
}
__device__ __forceinline__ uint32_t relu_add2(uint32_t v, uint32_t tv) {
    __half2 a = __hadd2(*(__half2*)&v, *(__half2*)&tv);
    __half2 z = __float2half2_rn(0.f);
    __half2 m = __hmax2(a, z);
    return *(uint32_t*)&m;
}
__device__ __forceinline__ void ldsm_x4(uint32_t& r0, uint32_t& r1, uint32_t& r2, uint32_t& r3,
                                        uint32_t addr) {
    asm volatile("ldmatrix.sync.aligned.m8n8.x4.shared.b16 {%0,%1,%2,%3}, [%4];"
                 : "=r"(r0), "=r"(r1), "=r"(r2), "=r"(r3) : "r"(addr));
}
__device__ __forceinline__ void mma_f16(float* c, const uint32_t* a,
                                        uint32_t b0, uint32_t b1) {
    asm volatile("mma.sync.aligned.m16n8k16.row.col.f32.f16.f16.f32 "
                 "{%0,%1,%2,%3},{%4,%5,%6,%7},{%8,%9},{%0,%1,%2,%3};"
                 : "+f"(c[0]), "+f"(c[1]), "+f"(c[2]), "+f"(c[3])
                 : "r"(a[0]), "r"(a[1]), "r"(a[2]), "r"(a[3]), "r"(b0), "r"(b1));
}

__global__ void __launch_bounds__(TPB, 1)
pairmlp_f16(const float* __restrict__ x, const float* __restrict__ y,
            const float* __restrict__ t, const float* __restrict__ W1,
            const float* __restrict__ b1, const float* __restrict__ W2,
            const float* __restrict__ b2, const float* __restrict__ W3,
            const float* __restrict__ b3, float* __restrict__ out)
{
    extern __shared__ char sm[];
    float* ys  = (float*)(sm + OB_YS);
    uint32_t* tv2 = (uint32_t*)(sm + OB_TV2);
    float* b2s = (float*)(sm + OB_B2S);
    float* w3s = (float*)(sm + OB_W3S);
    __half* w1t = (__half*)(sm + OB_W1T);
    __half* w2t = (__half*)(sm + OB_W2T);

    const int tid = threadIdx.x;
    const int wid = tid >> 5;
    const int l   = tid & 31;
    const int grp = wid >> 3;          // 0/1: which i of the pair
    const int m16 = (wid & 7) * 16;    // warp's 16 j-rows
    const uint32_t sb = smem_u32(sm);
    const uint32_t dhb = sb + (grp ? OB_DH1 : OB_DH0);

    // ---- one-time staging ----
    for (int idx = tid; idx < 64 * 128; idx += TPB) {
        int k = idx >> 7, n = idx & 127;
        w1t[n * 72 + k] = __float2half(W1[k * 128 + n]);
    }
    for (int idx = tid; idx < 128 * 128; idx += TPB) {
        int h = idx >> 7, n = idx & 127;
        w2t[n * 136 + h] = __float2half(W2[h * 128 + n]);
    }
    // tv packed as half2 per h-pair: tv2[b][h/2]
    for (int idx = tid; idx < 4 * 64; idx += TPB) {
        int bb = idx >> 6, hp = idx & 63;
        float s0 = b1[2 * hp], s1 = b1[2 * hp + 1];
        #pragma unroll
        for (int d = 0; d < 32; d++) {
            float tv = t[bb * 32 + d];
            s0 += tv * W1[(64 + d) * 128 + 2 * hp];
            s1 += tv * W1[(64 + d) * 128 + 2 * hp + 1];
        }
        tv2[bb * 64 + hp] = pack2(s0, s1);
    }
    if (tid < 128) { b2s[tid] = b2[tid]; w3s[tid] = W3[tid]; }
    const float b3v = b3[0];
    __syncthreads();

    // ---- per-lane ldmatrix addresses ----
    const int g2 = l >> 3, r = l & 7;
    const uint32_t aA = dhb + (uint32_t)(m16 + (g2 & 1) * 8 + r) * 144 + (uint32_t)(g2 >> 1) * 16;
    const uint32_t bB1 = sb + OB_W1T + (uint32_t)((g2 >> 1) * 8 + r) * 144 + (uint32_t)(g2 & 1) * 16;
    const uint32_t bB2 = sb + OB_W2T + (uint32_t)((g2 >> 1) * 8 + r) * 272 + (uint32_t)(g2 & 1) * 16;

    const int qr = l >> 2, qc = l & 3;
    const int start = (PT * blockIdx.x) / GRID;
    const int end   = (PT * (blockIdx.x + 1)) / GRID;
    int cur_bjt = -1;

    for (int tau = start; tau < end; ++tau) {
        const int b  = tau >> 10;
        const int jt = (tau >> 8) & 3;
        const int q  = tau & 255;
        const int i  = q * 2 + grp;
        const int bjt = tau >> 8;

        if (bjt != cur_bjt) {
            __syncthreads();
            const float4* yg = (const float4*)(y + ((size_t)(b * NN + jt * 128)) * 64);
            for (int idx = tid; idx < 128 * 16; idx += TPB) {
                int rr = idx >> 4, gg = idx & 15;
                float4 v = yg[rr * 16 + gg];
                float* dst = ys + rr * 68 + gg * 4;
                dst[0] = v.x; dst[1] = v.y; dst[2] = v.z; dst[3] = v.w;
            }
            cur_bjt = bjt;
            __syncthreads();
        }

        // ---- diff^2 -> DH strip (fp16), rows m16..m16+15, k-chunk qc*16 ----
        {
            const float4* xg = (const float4*)(x + ((size_t)(b * NN + i)) * 64 + qc * 16);
            float4 xv[4];
            #pragma unroll
            for (int qq = 0; qq < 4; qq++) xv[qq] = xg[qq];
            #pragma unroll
            for (int rr = 0; rr < 2; rr++) {
                int row = m16 + qr + rr * 8;
                const float4* yrow = (const float4*)(ys + row * 68 + qc * 16);
                uint32_t base = dhb - sb + (uint32_t)row * 144 + (uint32_t)qc * 32;
                uint32_t u[8];
                #pragma unroll
                for (int qq = 0; qq < 4; qq++) {
                    float4 yv = yrow[qq];
                    float d0 = xv[qq].x - yv.x, d1 = xv[qq].y - yv.y;
                    float d2 = xv[qq].z - yv.z, d3 = xv[qq].w - yv.w;
                    u[2 * qq]     = pack2(d0 * d0, d1 * d1);
                    u[2 * qq + 1] = pack2(d2 * d2, d3 * d3);
                }
                *(uint4*)(sm + base)      = make_uint4(u[0], u[1], u[2], u[3]);
                *(uint4*)(sm + base + 16) = make_uint4(u[4], u[5], u[6], u[7]);
            }
        }
        __syncwarp();

        // ---- preload GEMM1 A fragments (diff) ----
        uint32_t a1[4][4];
        #pragma unroll
        for (int ks = 0; ks < 4; ks++)
            ldsm_x4(a1[ks][0], a1[ks][1], a1[ks][2], a1[ks][3], aA + (uint32_t)ks * 32);

        // ---- GEMM1: M=16, N=128, K=64 ----
        float acc[16][4];
        #pragma unroll
        for (int nt = 0; nt < 16; nt++)
            #pragma unroll
            for (int c = 0; c < 4; c++) acc[nt][c] = 0.f;

        #pragma unroll
        for (int ks = 0; ks < 4; ks++) {
            #pragma unroll
            for (int p = 0; p < 8; p++) {
                uint32_t b0, b1v, b2v, b3r;
                ldsm_x4(b0, b1v, b2v, b3r, bB1 + (uint32_t)p * (16 * 144) + (uint32_t)ks * 32);
                mma_f16(acc[2 * p],     a1[ks], b0, b1v);
                mma_f16(acc[2 * p + 1], a1[ks], b2v, b3r);
            }
        }

        // ---- epilogue1 IN REGISTERS: af = relu(C1+tv) packed half2 ----
        uint32_t af[8][4];
        {
            const uint32_t* tvb = tv2 + b * 64;
            #pragma unroll
            for (int ks = 0; ks < 8; ks++) {
                uint32_t tv0 = tvb[ks * 8 + qc];        // h-pair (2ks)*8+2qc
                uint32_t tv1 = tvb[ks * 8 + 4 + qc];    // h-pair (2ks+1)*8+2qc
                af[ks][0] = relu_add2(pack2(acc[2 * ks][0],     acc[2 * ks][1]),     tv0);
                af[ks][1] = relu_add2(pack2(acc[2 * ks][2],     acc[2 * ks][3]),     tv0);
                af[ks][2] = relu_add2(pack2(acc[2 * ks + 1][0], acc[2 * ks + 1][1]), tv1);
                af[ks][3] = relu_add2(pack2(acc[2 * ks + 1][2], acc[2 * ks + 1][3]), tv1);
            }
        }

        // ---- GEMM2: M=16, N=128 (two n-halves), K=128; A from regs ----
        float part[2] = {0.f, 0.f};
        #pragma unroll
        for (int hf = 0; hf < 2; hf++) {
            float acc2[8][4];
            #pragma unroll
            for (int nt = 0; nt < 8; nt++)
                #pragma unroll
                for (int c = 0; c < 4; c++) acc2[nt][c] = 0.f;

            const uint32_t bbase = bB2 + (uint32_t)hf * (64 * 272);
            #pragma unroll
            for (int ks = 0; ks < 8; ks++) {
                #pragma unroll
                for (int p = 0; p < 4; p++) {
                    uint32_t b0, b1v, b2v, b3r;
                    ldsm_x4(b0, b1v, b2v, b3r, bbase + (uint32_t)p * (16 * 272) + (uint32_t)ks * 32);
                    mma_f16(acc2[2 * p],     af[ks], b0, b1v);
                    mma_f16(acc2[2 * p + 1], af[ks], b2v, b3r);
                }
            }
            const float* b2b = b2s + hf * 64;
            const float* w3b = w3s + hf * 64;
            #pragma unroll
            for (int nt = 0; nt < 8; nt++) {
                int h0 = nt * 8 + 2 * qc;
                float2 b2v = *(const float2*)(b2b + h0);
                float2 w3v = *(const float2*)(w3b + h0);
                part[0] += fmaxf(acc2[nt][0] + b2v.x, 0.f) * w3v.x
                         + fmaxf(acc2[nt][1] + b2v.y, 0.f) * w3v.y;
                part[1] += fmaxf(acc2[nt][2] + b2v.x, 0.f) * w3v.x
                         + fmaxf(acc2[nt][3] + b2v.y, 0.f) * w3v.y;
            }
        }

        #pragma unroll
        for (int p = 0; p < 2; p++) {
            part[p] += __shfl_xor_sync(0xffffffff, part[p], 1);
            part[p] += __shfl_xor_sync(0xffffffff, part[p], 2);
        }
        if (qc == 0) {
            size_t obase = ((size_t)(b * NN + i)) * NN + jt * 128 + m16;
            out[obase + qr]     = part[0] + b3v;
            out[obase + 8 + qr] = part[1] + b3v;
        }
    }
}

extern "C" void kernel_launch(void* const* d_in, const int* in_sizes, int n_in,
                              void* d_out, int out_size)
{
    const float* x  = (const float*)d_in[0];
    const float* y  = (const float*)d_in[1];
    const float* t  = (const float*)d_in[2];
    const float* W1 = (const float*)d_in[3];
    const float* b1 = (const float*)d_in[4];
    const float* W2 = (const float*)d_in[5];
    const float* b2 = (const float*)d_in[6];
    const float* W3 = (const float*)d_in[7];
    const float* b3 = (const float*)d_in[8];
    float* out = (float*)d_out;

    cudaFuncSetAttribute(pairmlp_f16,
                         cudaFuncAttributeMaxDynamicSharedMemorySize, SMEM_BYTES);
    pairmlp_f16<<<GRID, TPB, SMEM_BYTES>>>(x, y, t, W1, b1, W2, b2, W3, b3, out);
}

// round 9
// speedup vs baseline: 2.5921x; 1.1042x over previous
#include <cuda_runtime.h>
#include <cuda_fp16.h>
#include <cstdint>

#define NN 512
#define GRID 148
#define TPB 384
#define NT 2736   // 16 bjt x 171 i-triples

// ---- SMEM byte offsets ----
#define OB_W1T 0        // fp16 [n=128][k=64]  stride 72 fp16 (144B)  -> 18432
#define OB_W2T 18432    // fp16 [n=128][h=128] stride 136 fp16 (272B) -> 34816
#define OB_DH  53248    // fp16 diff [j=128][72] stride 144B, x3 groups -> 55296
#define OB_YS  108544   // f32 [128][68] -> 34816
#define OB_TV2 143360   // half2 tv [4][64] u32 -> 1024
#define OB_B2S 144384   // f32 [128]
#define OB_W3S 144896   // f32 [128]
#define SMEM_BYTES 145408

__device__ __forceinline__ uint32_t smem_u32(const void* p) {
    uint32_t a;
    asm("{ .reg .u64 t; cvta.to.shared.u64 t, %1; cvt.u32.u64 %0, t; }" : "=r"(a) : "l"(p));
    return a;
}
__device__ __forceinline__ uint32_t pack2(float e0, float e1) {
    __half2 h = __floats2half2_rn(e0, e1);
    return *(uint32_t*)&h;
}
__device__ __forceinline__ uint32_t relu_add2(uint32_t v, uint32_t tv) {
    __half2 a = __hadd2(*(__half2*)&v, *(__half2*)&tv);
    __half2 z = __float2half2_rn(0.f);
    __half2 m = __hmax2(a, z);
    return *(uint32_t*)&m;
}
__device__ __forceinline__ void ldsm_x4(uint32_t& r0, uint32_t& r1, uint32_t& r2, uint32_t& r3,
                                        uint32_t addr) {
    asm volatile("ldmatrix.sync.aligned.m8n8.x4.shared.b16 {%0,%1,%2,%3}, [%4];"
                 : "=r"(r0), "=r"(r1), "=r"(r2), "=r"(r3) : "r"(addr));
}
__device__ __forceinline__ void mma_f16(float* c, const uint32_t* a,
                                        uint32_t b0, uint32_t b1) {
    asm volatile("mma.sync.aligned.m16n8k16.row.col.f32.f16.f16.f32 "
                 "{%0,%1,%2,%3},{%4,%5,%6,%7},{%8,%9},{%0,%1,%2,%3};"
                 : "+f"(c[0]), "+f"(c[1]), "+f"(c[2]), "+f"(c[3])
                 : "r"(a[0]), "r"(a[1]), "r"(a[2]), "r"(a[3]), "r"(b0), "r"(b1));
}

__global__ void __launch_bounds__(TPB, 1)
pairmlp_f16(const float* __restrict__ x, const float* __restrict__ y,
            const float* __restrict__ t, const float* __restrict__ W1,
            const float* __restrict__ b1, const float* __restrict__ W2,
            const float* __restrict__ b2, const float* __restrict__ W3,
            const float* __restrict__ b3, float* __restrict__ out)
{
    extern __shared__ char sm[];
    float* ys  = (float*)(sm + OB_YS);
    uint32_t* tv2 = (uint32_t*)(sm + OB_TV2);
    float* b2s = (float*)(sm + OB_B2S);
    float* w3s = (float*)(sm + OB_W3S);
    __half* w1t = (__half*)(sm + OB_W1T);
    __half* w2t = (__half*)(sm + OB_W2T);

    const int tid = threadIdx.x;
    const int wid = tid >> 5;
    const int l   = tid & 31;
    const int grp = wid >> 2;          // 0..2: which i of the triple
    const int m32 = (wid & 3) * 32;    // warp's 32 j-rows
    const uint32_t sb = smem_u32(sm);
    const uint32_t dhb = sb + OB_DH + (uint32_t)grp * 18432u;

    // ---- one-time staging ----
    for (int idx = tid; idx < 64 * 128; idx += TPB) {
        int k = idx >> 7, n = idx & 127;
        w1t[n * 72 + k] = __float2half(W1[k * 128 + n]);
    }
    for (int idx = tid; idx < 128 * 128; idx += TPB) {
        int h = idx >> 7, n = idx & 127;
        w2t[n * 136 + h] = __float2half(W2[h * 128 + n]);
    }
    for (int idx = tid; idx < 4 * 64; idx += TPB) {
        int bb = idx >> 6, hp = idx & 63;
        float s0 = b1[2 * hp], s1 = b1[2 * hp + 1];
        #pragma unroll
        for (int d = 0; d < 32; d++) {
            float tv = t[bb * 32 + d];
            s0 += tv * W1[(64 + d) * 128 + 2 * hp];
            s1 += tv * W1[(64 + d) * 128 + 2 * hp + 1];
        }
        tv2[bb * 64 + hp] = pack2(s0, s1);
    }
    if (tid < 128) { b2s[tid] = b2[tid]; w3s[tid] = W3[tid]; }
    const float b3v = b3[0];
    __syncthreads();

    // ---- per-lane ldmatrix addresses ----
    const int g2 = l >> 3, r = l & 7;
    const uint32_t aA  = dhb + (uint32_t)(m32 + (g2 & 1) * 8 + r) * 144 + (uint32_t)(g2 >> 1) * 16;
    const uint32_t bB1 = sb + OB_W1T + (uint32_t)((g2 >> 1) * 8 + r) * 144 + (uint32_t)(g2 & 1) * 16;
    const uint32_t bB2 = sb + OB_W2T + (uint32_t)((g2 >> 1) * 8 + r) * 272 + (uint32_t)(g2 & 1) * 16;

    const int qr = l >> 2, qc = l & 3;
    const int start = (NT * blockIdx.x) / GRID;
    const int end   = (NT * (blockIdx.x + 1)) / GRID;
    int cur_bjt = -1;

    for (int tau = start; tau < end; ++tau) {
        const int bjt = tau / 171;
        const int q   = tau - bjt * 171;
        const int b   = bjt >> 2;
        const int jt  = bjt & 3;
        const int i   = q * 3 + grp;
        const int ild = (i < NN) ? i : (NN - 1);

        if (bjt != cur_bjt) {
            __syncthreads();
            const float4* yg = (const float4*)(y + ((size_t)(b * NN + jt * 128)) * 64);
            for (int idx = tid; idx < 128 * 16; idx += TPB) {
                int rr = idx >> 4, gg = idx & 15;
                float4 v = yg[rr * 16 + gg];
                float* dst = ys + rr * 68 + gg * 4;
                dst[0] = v.x; dst[1] = v.y; dst[2] = v.z; dst[3] = v.w;
            }
            cur_bjt = bjt;
            __syncthreads();
        }

        // ---- diff^2 -> DH strip (fp16), rows m32..m32+31, k-chunk qc*16 ----
        {
            const float4* xg = (const float4*)(x + ((size_t)(b * NN + ild)) * 64 + qc * 16);
            float4 xv[4];
            #pragma unroll
            for (int qq = 0; qq < 4; qq++) xv[qq] = xg[qq];
            #pragma unroll
            for (int rr = 0; rr < 4; rr++) {
                int row = m32 + qr + rr * 8;
                const float4* yrow = (const float4*)(ys + row * 68 + qc * 16);
                uint32_t base = dhb - sb + (uint32_t)row * 144 + (uint32_t)qc * 32;
                uint32_t u[8];
                #pragma unroll
                for (int qq = 0; qq < 4; qq++) {
                    float4 yv = yrow[qq];
                    float d0 = xv[qq].x - yv.x, d1 = xv[qq].y - yv.y;
                    float d2 = xv[qq].z - yv.z, d3 = xv[qq].w - yv.w;
                    u[2 * qq]     = pack2(d0 * d0, d1 * d1);
                    u[2 * qq + 1] = pack2(d2 * d2, d3 * d3);
                }
                *(uint4*)(sm + base)      = make_uint4(u[0], u[1], u[2], u[3]);
                *(uint4*)(sm + base + 16) = make_uint4(u[4], u[5], u[6], u[7]);
            }
        }
        __syncwarp();

        // ---- preload GEMM1 A fragments (diff), 2 m-blocks x 4 k-steps ----
        uint32_t a1[2][4][4];
        #pragma unroll
        for (int mb = 0; mb < 2; mb++)
            #pragma unroll
            for (int ks = 0; ks < 4; ks++)
                ldsm_x4(a1[mb][ks][0], a1[mb][ks][1], a1[mb][ks][2], a1[mb][ks][3],
                        aA + (uint32_t)mb * (16 * 144) + (uint32_t)ks * 32);

        // ---- GEMM1 (M=32, K=64) in 2 n-halves; epilogue1 -> af in registers ----
        uint32_t af[2][8][4];
        #pragma unroll
        for (int hf = 0; hf < 2; hf++) {
            float acc[2][8][4];
            #pragma unroll
            for (int mb = 0; mb < 2; mb++)
                #pragma unroll
                for (int nt = 0; nt < 8; nt++)
                    #pragma unroll
                    for (int c = 0; c < 4; c++) acc[mb][nt][c] = 0.f;

            const uint32_t bbase = bB1 + (uint32_t)hf * (64 * 144);
            #pragma unroll
            for (int ks = 0; ks < 4; ks++) {
                #pragma unroll
                for (int p = 0; p < 4; p++) {
                    uint32_t b0, b1v, b2v, b3r;
                    ldsm_x4(b0, b1v, b2v, b3r, bbase + (uint32_t)p * (16 * 144) + (uint32_t)ks * 32);
                    mma_f16(acc[0][2 * p],     a1[0][ks], b0, b1v);
                    mma_f16(acc[0][2 * p + 1], a1[0][ks], b2v, b3r);
                    mma_f16(acc[1][2 * p],     a1[1][ks], b0, b1v);
                    mma_f16(acc[1][2 * p + 1], a1[1][ks], b2v, b3r);
                }
            }
            // C1 (m16n8) frags -> GEMM2 A (m16k16) frags, relu(+tv), packed half2
            const uint32_t* tvb = tv2 + b * 64;
            #pragma unroll
            for (int ks2 = 0; ks2 < 4; ks2++) {
                int ksg = 4 * hf + ks2;                 // global k16 block of GEMM2
                uint32_t tv0 = tvb[(8 * hf + 2 * ks2) * 4 + qc];
                uint32_t tv1 = tvb[(8 * hf + 2 * ks2 + 1) * 4 + qc];
                #pragma unroll
                for (int mb = 0; mb < 2; mb++) {
                    af[mb][ksg][0] = relu_add2(pack2(acc[mb][2 * ks2][0],     acc[mb][2 * ks2][1]),     tv0);
                    af[mb][ksg][1] = relu_add2(pack2(acc[mb][2 * ks2][2],     acc[mb][2 * ks2][3]),     tv0);
                    af[mb][ksg][2] = relu_add2(pack2(acc[mb][2 * ks2 + 1][0], acc[mb][2 * ks2 + 1][1]), tv1);
                    af[mb][ksg][3] = relu_add2(pack2(acc[mb][2 * ks2 + 1][2], acc[mb][2 * ks2 + 1][3]), tv1);
                }
            }
        }

        // ---- GEMM2 (M=32, K=128) in 2 n-halves; fused epilogue2 ----
        float part[4] = {0.f, 0.f, 0.f, 0.f};
        #pragma unroll
        for (int hf = 0; hf < 2; hf++) {
            float acc2[2][8][4];
            #pragma unroll
            for (int mb = 0; mb < 2; mb++)
                #pragma unroll
                for (int nt = 0; nt < 8; nt++)
                    #pragma unroll
                    for (int c = 0; c < 4; c++) acc2[mb][nt][c] = 0.f;

            const uint32_t bbase = bB2 + (uint32_t)hf * (64 * 272);
            #pragma unroll
            for (int ks = 0; ks < 8; ks++) {
                #pragma unroll
                for (int p = 0; p < 4; p++) {
                    uint32_t b0, b1v, b2v, b3r;
                    ldsm_x4(b0, b1v, b2v, b3r, bbase + (uint32_t)p * (16 * 272) + (uint32_t)ks * 32);
                    mma_f16(acc2[0][2 * p],     af[0][ks], b0, b1v);
                    mma_f16(acc2[0][2 * p + 1], af[0][ks], b2v, b3r);
                    mma_f16(acc2[1][2 * p],     af[1][ks], b0, b1v);
                    mma_f16(acc2[1][2 * p + 1], af[1][ks], b2v, b3r);
                }
            }
            const float* b2b = b2s + hf * 64;
            const float* w3b = w3s + hf * 64;
            #pragma unroll
            for (int nt = 0; nt < 8; nt++) {
                int h0 = nt * 8 + 2 * qc;
                float2 b2v = *(const float2*)(b2b + h0);
                float2 w3v = *(const float2*)(w3b + h0);
                #pragma unroll
                for (int mb = 0; mb < 2; mb++) {
                    part[mb * 2]     += fmaxf(acc2[mb][nt][0] + b2v.x, 0.f) * w3v.x
                                      + fmaxf(acc2[mb][nt][1] + b2v.y, 0.f) * w3v.y;
                    part[mb * 2 + 1] += fmaxf(acc2[mb][nt][2] + b2v.x, 0.f) * w3v.x
                                      + fmaxf(acc2[mb][nt][3] + b2v.y, 0.f) * w3v.y;
                }
            }
        }

        #pragma unroll
        for (int p = 0; p < 4; p++) {
            part[p] += __shfl_xor_sync(0xffffffff, part[p], 1);
            part[p] += __shfl_xor_sync(0xffffffff, part[p], 2);
        }
        if (qc == 0 && i < NN) {
            size_t obase = ((size_t)(b * NN + i)) * NN + jt * 128 + m32;
            out[obase + qr]      = part[0] + b3v;
            out[obase + 8 + qr]  = part[1] + b3v;
            out[obase + 16 + qr] = part[2] + b3v;
            out[obase + 24 + qr] = part[3] + b3v;
        }
    }
}

extern "C" void kernel_launch(void* const* d_in, const int* in_sizes, int n_in,
                              void* d_out, int out_size)
{
    const float* x  = (const float*)d_in[0];
    const float* y  = (const float*)d_in[1];
    const float* t  = (const float*)d_in[2];
    const float* W1 = (const float*)d_in[3];
    const float* b1 = (const float*)d_in[4];
    const float* W2 = (const float*)d_in[5];
    const float* b2 = (const float*)d_in[6];
    const float* W3 = (const float*)d_in[7];
    const float* b3 = (const float*)d_in[8];
    float* out = (float*)d_out;

    cudaFuncSetAttribute(pairmlp_f16,
                         cudaFuncAttributeMaxDynamicSharedMemorySize, SMEM_BYTES);
    pairmlp_f16<<<GRID, TPB, SMEM_BYTES>>>(x, y, t, W1, b1, W2, b2, W3, b3, out);
}

// round 10
// speedup vs baseline: 2.6957x; 1.0400x over previous
#include <cuda_runtime.h>
#include <cuda_fp16.h>
#include <cstdint>

#define NN 512
#define GRID 148
#define TPB 512
#define NT 2048   // 4 b x 4 jt x 128 i-quads

// ---- SMEM byte offsets ----
#define OB_W1T 0        // fp16 [n=128][k=64]  stride 72 fp16 (144B)  -> 18432
#define OB_W2T 18432    // fp16 [n=128][h=128] stride 136 fp16 (272B) -> 34816
#define OB_DH  53248    // fp16 diff [j=128][72] stride 144B, x4 groups -> 73728
#define OB_YS  126976   // f32 [128][68] -> 34816
#define OB_TV2 161792   // half2 tv [4][64] u32 -> 1024
#define OB_B2S 162816   // f32 [128]
#define OB_W3S 163328   // f32 [128]
#define SMEM_BYTES 163840

__device__ __forceinline__ uint32_t smem_u32(const void* p) {
    uint32_t a;
    asm("{ .reg .u64 t; cvta.to.shared.u64 t, %1; cvt.u32.u64 %0, t; }" : "=r"(a) : "l"(p));
    return a;
}
__device__ __forceinline__ uint32_t pack2(float e0, float e1) {
    __half2 h = __floats2half2_rn(e0, e1);
    return *(uint32_t*)&h;
}
__device__ __forceinline__ uint32_t relu_add2(uint32_t v, uint32_t tv) {
    __half2 a = __hadd2(*(__half2*)&v, *(__half2*)&tv);
    __half2 z = __float2half2_rn(0.f);
    __half2 m = __hmax2(a, z);
    return *(uint32_t*)&m;
}
__device__ __forceinline__ void ldsm_x4(uint32_t& r0, uint32_t& r1, uint32_t& r2, uint32_t& r3,
                                        uint32_t addr) {
    asm volatile("ldmatrix.sync.aligned.m8n8.x4.shared.b16 {%0,%1,%2,%3}, [%4];"
                 : "=r"(r0), "=r"(r1), "=r"(r2), "=r"(r3) : "r"(addr));
}
__device__ __forceinline__ void mma_f16(float* c, const uint32_t* a,
                                        uint32_t b0, uint32_t b1) {
    asm volatile("mma.sync.aligned.m16n8k16.row.col.f32.f16.f16.f32 "
                 "{%0,%1,%2,%3},{%4,%5,%6,%7},{%8,%9},{%0,%1,%2,%3};"
                 : "+f"(c[0]), "+f"(c[1]), "+f"(c[2]), "+f"(c[3])
                 : "r"(a[0]), "r"(a[1]), "r"(a[2]), "r"(a[3]), "r"(b0), "r"(b1));
}

__global__ void __launch_bounds__(TPB, 1)
pairmlp_f16(const float* __restrict__ x, const float* __restrict__ y,
            const float* __restrict__ t, const float* __restrict__ W1,
            const float* __restrict__ b1, const float* __restrict__ W2,
            const float* __restrict__ b2, const float* __restrict__ W3,
            const float* __restrict__ b3, float* __restrict__ out)
{
    extern __shared__ char sm[];
    float* ys  = (float*)(sm + OB_YS);
    uint32_t* tv2 = (uint32_t*)(sm + OB_TV2);
    float* b2s = (float*)(sm + OB_B2S);
    float* w3s = (float*)(sm + OB_W3S);
    __half* w1t = (__half*)(sm + OB_W1T);
    __half* w2t = (__half*)(sm + OB_W2T);

    const int tid = threadIdx.x;
    const int wid = tid >> 5;
    const int l   = tid & 31;
    const int grp = wid >> 2;          // 0..3: which i of the quad
    const int m32 = (wid & 3) * 32;    // warp's 32 j-rows
    const uint32_t sb = smem_u32(sm);
    const uint32_t dhb = sb + OB_DH + (uint32_t)grp * 18432u;

    // ---- one-time staging ----
    for (int idx = tid; idx < 64 * 128; idx += TPB) {
        int k = idx >> 7, n = idx & 127;
        w1t[n * 72 + k] = __float2half(W1[k * 128 + n]);
    }
    for (int idx = tid; idx < 128 * 128; idx += TPB) {
        int h = idx >> 7, n = idx & 127;
        w2t[n * 136 + h] = __float2half(W2[h * 128 + n]);
    }
    for (int idx = tid; idx < 4 * 64; idx += TPB) {
        int bb = idx >> 6, hp = idx & 63;
        float s0 = b1[2 * hp], s1 = b1[2 * hp + 1];
        #pragma unroll
        for (int d = 0; d < 32; d++) {
            float tv = t[bb * 32 + d];
            s0 += tv * W1[(64 + d) * 128 + 2 * hp];
            s1 += tv * W1[(64 + d) * 128 + 2 * hp + 1];
        }
        tv2[bb * 64 + hp] = pack2(s0, s1);
    }
    if (tid < 128) { b2s[tid] = b2[tid]; w3s[tid] = W3[tid]; }
    const float b3v = b3[0];
    __syncthreads();

    // ---- per-lane ldmatrix addresses ----
    const int g2 = l >> 3, r = l & 7;
    const uint32_t aA  = dhb + (uint32_t)(m32 + (g2 & 1) * 8 + r) * 144 + (uint32_t)(g2 >> 1) * 16;
    const uint32_t bB1 = sb + OB_W1T + (uint32_t)((g2 >> 1) * 8 + r) * 144 + (uint32_t)(g2 & 1) * 16;
    const uint32_t bB2 = sb + OB_W2T + (uint32_t)((g2 >> 1) * 8 + r) * 272 + (uint32_t)(g2 & 1) * 16;

    const int qr = l >> 2, qc = l & 3;
    const int start = (NT * blockIdx.x) / GRID;
    const int end   = (NT * (blockIdx.x + 1)) / GRID;
    int cur_bjt = -1;

    for (int tau = start; tau < end; ++tau) {
        const int bjt = tau >> 7;          // 0..15
        const int q   = tau & 127;
        const int b   = bjt >> 2;
        const int jt  = bjt & 3;
        const int i   = q * 4 + grp;       // always < 512

        if (bjt != cur_bjt) {
            __syncthreads();
            const float4* yg = (const float4*)(y + ((size_t)(b * NN + jt * 128)) * 64);
            for (int idx = tid; idx < 128 * 16; idx += TPB) {
                int rr = idx >> 4, gg = idx & 15;
                float4 v = yg[rr * 16 + gg];
                float* dst = ys + rr * 68 + gg * 4;
                dst[0] = v.x; dst[1] = v.y; dst[2] = v.z; dst[3] = v.w;
            }
            cur_bjt = bjt;
            __syncthreads();
        }

        // ---- diff^2 -> DH strip (fp16), rows m32..m32+31, k-chunk qc*16 ----
        {
            const float4* xg = (const float4*)(x + ((size_t)(b * NN + i)) * 64 + qc * 16);
            float4 xv[4];
            #pragma unroll
            for (int qq = 0; qq < 4; qq++) xv[qq] = xg[qq];
            #pragma unroll
            for (int rr = 0; rr < 4; rr++) {
                int row = m32 + qr + rr * 8;
                const float4* yrow = (const float4*)(ys + row * 68 + qc * 16);
                uint32_t base = dhb - sb + (uint32_t)row * 144 + (uint32_t)qc * 32;
                uint32_t u[8];
                #pragma unroll
                for (int qq = 0; qq < 4; qq++) {
                    float4 yv = yrow[qq];
                    float d0 = xv[qq].x - yv.x, d1 = xv[qq].y - yv.y;
                    float d2 = xv[qq].z - yv.z, d3 = xv[qq].w - yv.w;
                    u[2 * qq]     = pack2(d0 * d0, d1 * d1);
                    u[2 * qq + 1] = pack2(d2 * d2, d3 * d3);
                }
                *(uint4*)(sm + base)      = make_uint4(u[0], u[1], u[2], u[3]);
                *(uint4*)(sm + base + 16) = make_uint4(u[4], u[5], u[6], u[7]);
            }
        }
        __syncwarp();

        // ---- preload GEMM1 A fragments (diff), 2 m-blocks x 4 k-steps ----
        uint32_t a1[2][4][4];
        #pragma unroll
        for (int mb = 0; mb < 2; mb++)
            #pragma unroll
            for (int ks = 0; ks < 4; ks++)
                ldsm_x4(a1[mb][ks][0], a1[mb][ks][1], a1[mb][ks][2], a1[mb][ks][3],
                        aA + (uint32_t)mb * (16 * 144) + (uint32_t)ks * 32);

        // ---- GEMM1 (M=32, K=64) in 4 n-quarters; epilogue1 -> af in regs ----
        uint32_t af[2][8][4];
        #pragma unroll
        for (int nq = 0; nq < 4; nq++) {
            float acc[2][4][4];
            #pragma unroll
            for (int mb = 0; mb < 2; mb++)
                #pragma unroll
                for (int nt = 0; nt < 4; nt++)
                    #pragma unroll
                    for (int c = 0; c < 4; c++) acc[mb][nt][c] = 0.f;

            const uint32_t bbase = bB1 + (uint32_t)nq * (32 * 144);
            #pragma unroll
            for (int ks = 0; ks < 4; ks++) {
                #pragma unroll
                for (int p = 0; p < 2; p++) {
                    uint32_t b0, b1v, b2v, b3r;
                    ldsm_x4(b0, b1v, b2v, b3r, bbase + (uint32_t)p * (16 * 144) + (uint32_t)ks * 32);
                    mma_f16(acc[0][2 * p],     a1[0][ks], b0, b1v);
                    mma_f16(acc[0][2 * p + 1], a1[0][ks], b2v, b3r);
                    mma_f16(acc[1][2 * p],     a1[1][ks], b0, b1v);
                    mma_f16(acc[1][2 * p + 1], a1[1][ks], b2v, b3r);
                }
            }
            // convert quarter to af k-blocks 2nq, 2nq+1
            const uint32_t* tvb = tv2 + b * 64;
            #pragma unroll
            for (int j = 0; j < 2; j++) {
                int ksg = 2 * nq + j;
                uint32_t tv0 = tvb[(4 * nq + 2 * j) * 4 + qc];
                uint32_t tv1 = tvb[(4 * nq + 2 * j + 1) * 4 + qc];
                #pragma unroll
                for (int mb = 0; mb < 2; mb++) {
                    af[mb][ksg][0] = relu_add2(pack2(acc[mb][2 * j][0],     acc[mb][2 * j][1]),     tv0);
                    af[mb][ksg][1] = relu_add2(pack2(acc[mb][2 * j][2],     acc[mb][2 * j][3]),     tv0);
                    af[mb][ksg][2] = relu_add2(pack2(acc[mb][2 * j + 1][0], acc[mb][2 * j + 1][1]), tv1);
                    af[mb][ksg][3] = relu_add2(pack2(acc[mb][2 * j + 1][2], acc[mb][2 * j + 1][3]), tv1);
                }
            }
        }

        // ---- GEMM2 (M=32, K=128) in 4 n-quarters; fused epilogue2 ----
        float part[4] = {0.f, 0.f, 0.f, 0.f};
        #pragma unroll
        for (int nq = 0; nq < 4; nq++) {
            float acc2[2][4][4];
            #pragma unroll
            for (int mb = 0; mb < 2; mb++)
                #pragma unroll
                for (int nt = 0; nt < 4; nt++)
                    #pragma unroll
                    for (int c = 0; c < 4; c++) acc2[mb][nt][c] = 0.f;

            const uint32_t bbase = bB2 + (uint32_t)nq * (32 * 272);
            #pragma unroll
            for (int ks = 0; ks < 8; ks++) {
                #pragma unroll
                for (int p = 0; p < 2; p++) {
                    uint32_t b0, b1v, b2v, b3r;
                    ldsm_x4(b0, b1v, b2v, b3r, bbase + (uint32_t)p * (16 * 272) + (uint32_t)ks * 32);
                    mma_f16(acc2[0][2 * p],     af[0][ks], b0, b1v);
                    mma_f16(acc2[0][2 * p + 1], af[0][ks], b2v, b3r);
                    mma_f16(acc2[1][2 * p],     af[1][ks], b0, b1v);
                    mma_f16(acc2[1][2 * p + 1], af[1][ks], b2v, b3r);
                }
            }
            const float* b2b = b2s + nq * 32;
            const float* w3b = w3s + nq * 32;
            #pragma unroll
            for (int nt = 0; nt < 4; nt++) {
                int h0 = nt * 8 + 2 * qc;
                float2 b2v = *(const float2*)(b2b + h0);
                float2 w3v = *(const float2*)(w3b + h0);
                #pragma unroll
                for (int mb = 0; mb < 2; mb++) {
                    part[mb * 2]     += fmaxf(acc2[mb][nt][0] + b2v.x, 0.f) * w3v.x
                                      + fmaxf(acc2[mb][nt][1] + b2v.y, 0.f) * w3v.y;
                    part[mb * 2 + 1] += fmaxf(acc2[mb][nt][2] + b2v.x, 0.f) * w3v.x
                                      + fmaxf(acc2[mb][nt][3] + b2v.y, 0.f) * w3v.y;
                }
            }
        }

        #pragma unroll
        for (int p = 0; p < 4; p++) {
            part[p] += __shfl_xor_sync(0xffffffff, part[p], 1);
            part[p] += __shfl_xor_sync(0xffffffff, part[p], 2);
        }
        if (qc == 0) {
            size_t obase = ((size_t)(b * NN + i)) * NN + jt * 128 + m32;
            out[obase + qr]      = part[0] + b3v;
            out[obase + 8 + qr]  = part[1] + b3v;
            out[obase + 16 + qr] = part[2] + b3v;
            out[obase + 24 + qr] = part[3] + b3v;
        }
    }
}

extern "C" void kernel_launch(void* const* d_in, const int* in_sizes, int n_in,
                              void* d_out, int out_size)
{
    const float* x  = (const float*)d_in[0];
    const float* y  = (const float*)d_in[1];
    const float* t  = (const float*)d_in[2];
    const float* W1 = (const float*)d_in[3];
    const float* b1 = (const float*)d_in[4];
    const float* W2 = (const float*)d_in[5];
    const float* b2 = (const float*)d_in[6];
    const float* W3 = (const float*)d_in[7];
    const float* b3 = (const float*)d_in[8];
    float* out = (float*)d_out;

    cudaFuncSetAttribute(pairmlp_f16,
                         cudaFuncAttributeMaxDynamicSharedMemorySize, SMEM_BYTES);
    pairmlp_f16<<<GRID, TPB, SMEM_BYTES>>>(x, y, t, W1, b1, W2, b2, W3, b3, out);
}